// round 1
// baseline (speedup 1.0000x reference)
#include <cuda_runtime.h>

#define NB   4
#define CCH  512
#define NPIX 2304
#define CR   64
#define CH4  128
#define HW   48
#define PADW 50

// ---------------- scratch (device globals; no dynamic allocation) ----------------
__device__ float g_q[NB*CR*NPIX];
__device__ float g_k[NB*CR*NPIX];
__device__ float g_v[NB*CCH*NPIX];
__device__ float g_E[(size_t)NB*NPIX*NPIX];      // energy
__device__ float g_A[(size_t)NB*NPIX*NPIX];      // materialized attention (reused per pass)
__device__ float g_stats[6*NB*NPIX];             // [variant][max|invsum][B*N]
__device__ float g_buf0[NB*CCH*NPIX];            // out0 (post conv1)
__device__ float g_buf1[NB*CCH*NPIX];            // pre-conv temp
__device__ float g_out1[NB*CCH*NPIX];            // out1 (post conv2)
__device__ float g_vchl[NB*CCH*NPIX];            // chl output (v1 / v2)
__device__ float g_pad[NB*CCH*PADW*PADW];        // zero-padded conv input
__device__ float g_qc[NB*CH4*NPIX];
__device__ float g_E2[NB*CH4*CCH];
__device__ float g_expand[NB*CCH*CCH];
__device__ float g_attnc[NB*CCH*CCH];
__device__ float g_wt1[CCH*9*CCH];               // conv1 weights as [ic][kk][oc]
__device__ float g_wt2[CCH*9*CCH];

// ---------------- reductions ----------------
__device__ __forceinline__ float warpMax(float v){
  #pragma unroll
  for (int o=16;o;o>>=1) v = fmaxf(v, __shfl_xor_sync(0xffffffffu, v, o));
  return v;
}
__device__ __forceinline__ float warpMin(float v){
  #pragma unroll
  for (int o=16;o;o>>=1) v = fminf(v, __shfl_xor_sync(0xffffffffu, v, o));
  return v;
}
__device__ __forceinline__ float warpSum(float v){
  #pragma unroll
  for (int o=16;o;o>>=1) v += __shfl_xor_sync(0xffffffffu, v, o);
  return v;
}
__device__ float blockMax(float v, float* sh){
  v = warpMax(v);
  if ((threadIdx.x & 31) == 0) sh[threadIdx.x >> 5] = v;
  __syncthreads();
  if (threadIdx.x < 32){
    float t = (threadIdx.x < (blockDim.x>>5)) ? sh[threadIdx.x] : -3.4e38f;
    t = warpMax(t);
    if (threadIdx.x == 0) sh[0] = t;
  }
  __syncthreads();
  float r = sh[0];
  __syncthreads();
  return r;
}
__device__ float blockMin(float v, float* sh){
  v = warpMin(v);
  if ((threadIdx.x & 31) == 0) sh[threadIdx.x >> 5] = v;
  __syncthreads();
  if (threadIdx.x < 32){
    float t = (threadIdx.x < (blockDim.x>>5)) ? sh[threadIdx.x] : 3.4e38f;
    t = warpMin(t);
    if (threadIdx.x == 0) sh[0] = t;
  }
  __syncthreads();
  float r = sh[0];
  __syncthreads();
  return r;
}
__device__ float blockSum(float v, float* sh){
  v = warpSum(v);
  if ((threadIdx.x & 31) == 0) sh[threadIdx.x >> 5] = v;
  __syncthreads();
  if (threadIdx.x < 32){
    float t = (threadIdx.x < (blockDim.x>>5)) ? sh[threadIdx.x] : 0.f;
    t = warpSum(t);
    if (threadIdx.x == 0) sh[0] = t;
  }
  __syncthreads();
  float r = sh[0];
  __syncthreads();
  return r;
}

// ---------------- generic tiled SGEMM ----------------
// MODE 0 = NN (A: MxK, B: KxN), 1 = TN (A: KxM, B: KxN), 2 = NT (A: MxK, B: NxK)
// EPI  0 = optional per-row bias; 1 = relu(acc*p0[m]+p1[m]); 2 = gamma[0]*acc + res[m,n]
// Requirements used here: N % 128 == 0, K % 16 == 0. M guarded.
template<int MODE, int EPI>
__global__ __launch_bounds__(256) void gemm_kernel(
    const float* __restrict__ A, long sA,
    const float* __restrict__ Bm, long sB,
    float* __restrict__ Cm, long sC,
    int M, int N, int K,
    const float* __restrict__ p0, const float* __restrict__ p1,
    const float* __restrict__ res, long sRes,
    const float* __restrict__ gamma)
{
  const int b = blockIdx.z;
  A  += (long)b * sA;
  Bm += (long)b * sB;
  Cm += (long)b * sC;
  if (EPI == 2) res += (long)b * sRes;

  __shared__ float As[16][132];
  __shared__ float Bs[16][132];

  const int tid = threadIdx.x;
  const int tr = (tid >> 4) * 8;
  const int tc = (tid & 15) * 8;
  const int m0 = blockIdx.y * 128;
  const int n0 = blockIdx.x * 128;

  float acc[8][8];
  #pragma unroll
  for (int i=0;i<8;i++)
    #pragma unroll
    for (int j=0;j<8;j++) acc[i][j]=0.f;

  for (int k0 = 0; k0 < K; k0 += 16){
    // ---- load A tile into As[k][m]
    if (MODE == 0 || MODE == 2){
      const int arow = tid >> 2;
      const int acol = (tid & 3) * 4;
      #pragma unroll
      for (int r = 0; r < 128; r += 64){
        int m = m0 + arow + r;
        float4 v = make_float4(0.f,0.f,0.f,0.f);
        if (m < M) v = *(const float4*)&A[(long)m * K + k0 + acol];
        As[acol+0][arow+r] = v.x;
        As[acol+1][arow+r] = v.y;
        As[acol+2][arow+r] = v.z;
        As[acol+3][arow+r] = v.w;
      }
    } else {
      const int ak = tid >> 5;
      const int am = (tid & 31) * 4;
      #pragma unroll
      for (int r = 0; r < 16; r += 8){
        float4 v = make_float4(0.f,0.f,0.f,0.f);
        if (m0 + am < M) v = *(const float4*)&A[(long)(k0 + ak + r) * M + m0 + am];
        *(float4*)&As[ak+r][am] = v;
      }
    }
    // ---- load B tile into Bs[k][n]
    if (MODE == 0 || MODE == 1){
      const int bk = tid >> 5;
      const int bn = (tid & 31) * 4;
      #pragma unroll
      for (int r = 0; r < 16; r += 8){
        float4 v = *(const float4*)&Bm[(long)(k0 + bk + r) * N + n0 + bn];
        *(float4*)&Bs[bk+r][bn] = v;
      }
    } else {
      const int brow = tid >> 2;
      const int bcol = (tid & 3) * 4;
      #pragma unroll
      for (int r = 0; r < 128; r += 64){
        int n = n0 + brow + r;
        float4 v = *(const float4*)&Bm[(long)n * K + k0 + bcol];
        Bs[bcol+0][brow+r] = v.x;
        Bs[bcol+1][brow+r] = v.y;
        Bs[bcol+2][brow+r] = v.z;
        Bs[bcol+3][brow+r] = v.w;
      }
    }
    __syncthreads();

    #pragma unroll
    for (int kk = 0; kk < 16; kk++){
      float a[8], bb[8];
      #pragma unroll
      for (int i=0;i<8;i++) a[i]  = As[kk][tr+i];
      #pragma unroll
      for (int j=0;j<8;j++) bb[j] = Bs[kk][tc+j];
      #pragma unroll
      for (int i=0;i<8;i++)
        #pragma unroll
        for (int j=0;j<8;j++) acc[i][j] += a[i]*bb[j];
    }
    __syncthreads();
  }

  #pragma unroll
  for (int i=0;i<8;i++){
    int m = m0 + tr + i;
    if (m < M){
      #pragma unroll
      for (int j=0;j<8;j++){
        int n = n0 + tc + j;
        float v = acc[i][j];
        if (EPI == 0){ if (p0) v += p0[m]; }
        else if (EPI == 1){ v = fmaxf(v * p0[m] + p1[m], 0.f); }
        else { v = gamma[0]*v + res[(long)m * N + n]; }
        Cm[(long)m * N + n] = v;
      }
    }
  }
}

// ---------------- softmax row stats (3 variants, one pass) ----------------
__global__ __launch_bounds__(256) void softmax_stats_kernel(
    const float* __restrict__ E, const float* __restrict__ M1,
    const float* __restrict__ M2, float* __restrict__ st)
{
  __shared__ float sh[32];
  const int R = NB*NPIX;
  int row = blockIdx.x;            // b*N + m
  int mr  = row % NPIX;
  const float* e  = E  + (long)row * NPIX;
  const float* m1 = M1 + (long)mr  * NPIX;
  const float* m2 = M2 + (long)mr  * NPIX;
  int tid = threadIdx.x;

  float ev[9], w1[9], w2[9];
  float mx0=-3.4e38f, mx1=-3.4e38f, mx2=-3.4e38f;
  #pragma unroll
  for (int i=0;i<9;i++){
    int n = tid + i*256;
    ev[i]=e[n]; w1[i]=m1[n]; w2[i]=m2[n];
    mx0 = fmaxf(mx0, ev[i]);
    if (w1[i] > 0.f) mx1 = fmaxf(mx1, ev[i]);
    if (w2[i] > 0.f) mx2 = fmaxf(mx2, ev[i]);
  }
  mx0 = blockMax(mx0, sh);
  mx1 = blockMax(mx1, sh);
  mx2 = blockMax(mx2, sh);
  float s0=0.f, s1=0.f, s2=0.f;
  #pragma unroll
  for (int i=0;i<9;i++){
    s0 += __expf(ev[i]-mx0);
    s1 += (w1[i] > 0.f) ? __expf(ev[i]-mx1) : 0.f;
    s2 += (w2[i] > 0.f) ? __expf(ev[i]-mx2) : 0.f;
  }
  s0 = blockSum(s0, sh);
  s1 = blockSum(s1, sh);
  s2 = blockSum(s2, sh);
  if (tid == 0){
    st[row]       = mx0;  st[R   + row] = 1.f/s0;
    st[2*R + row] = mx1;  st[3*R + row] = 1.f/s1;
    st[4*R + row] = mx2;  st[5*R + row] = 1.f/s2;
  }
}

// ---------------- materialize attention matrix ----------------
__global__ __launch_bounds__(256) void attn_mat_kernel(
    const float* __restrict__ E, const float* __restrict__ mask,
    const float* __restrict__ st, float* __restrict__ A, long total4)
{
  const long NN2 = (long)NPIX*NPIX;
  long i4 = (long)blockIdx.x * 256 + threadIdx.x;
  if (i4 >= total4) return;
  long idx = i4 * 4;
  int  b   = (int)(idx / NN2);
  long rem = idx - (long)b * NN2;
  int  mr  = (int)(rem / NPIX);
  float mx   = st[b*NPIX + mr];
  float rinv = st[NB*NPIX + b*NPIX + mr];
  float4 e = *(const float4*)&E[idx];
  float4 a;
  a.x = __expf(e.x-mx)*rinv;
  a.y = __expf(e.y-mx)*rinv;
  a.z = __expf(e.z-mx)*rinv;
  a.w = __expf(e.w-mx)*rinv;
  if (mask){
    float4 mk = *(const float4*)&mask[rem];
    if (mk.x <= 0.f) a.x = 0.f;
    if (mk.y <= 0.f) a.y = 0.f;
    if (mk.z <= 0.f) a.z = 0.f;
    if (mk.w <= 0.f) a.w = 0.f;
  }
  *(float4*)&A[idx] = a;
}

// ---------------- chl softmax: attn[o,c] = softmax_c(rowmax - expand[o,c]) ----------------
__global__ __launch_bounds__(256) void chl_softmax_kernel(
    const float* __restrict__ E, float* __restrict__ A)
{
  __shared__ float sh[32];
  long row = blockIdx.x;
  const float* e = E + row * CCH;
  float* a = A + row * CCH;
  int tid = threadIdx.x;
  float v0 = e[tid], v1 = e[tid+256];
  float mn = blockMin(fminf(v0, v1), sh);   // softmax(max-e) == exp(mn-e)/sum
  float t0 = __expf(mn - v0), t1 = __expf(mn - v1);
  float s = blockSum(t0 + t1, sh);
  float rinv = 1.f/s;
  a[tid]     = t0*rinv;
  a[tid+256] = t1*rinv;
}

// ---------------- conv helpers ----------------
__global__ __launch_bounds__(256) void wtrans_kernel(const float* __restrict__ W, float* __restrict__ Wt){
  int idx = blockIdx.x*256 + threadIdx.x;
  if (idx >= CCH*CCH*9) return;
  int oc = idx / (CCH*9);
  int r  = idx - oc*(CCH*9);
  int ic = r / 9;
  int kk = r - ic*9;
  Wt[(long)ic*9*CCH + kk*CCH + oc] = W[idx];
}

__global__ __launch_bounds__(256) void pad_kernel(const float* __restrict__ X, float* __restrict__ Xp){
  long total = (long)NB*CCH*PADW*PADW;
  for (long idx = (long)blockIdx.x*256 + threadIdx.x; idx < total; idx += (long)gridDim.x*256){
    long plane = idx / (PADW*PADW);
    int r = (int)(idx - plane*(PADW*PADW));
    int y = r / PADW, x = r - y*PADW;
    float v = 0.f;
    if (y >= 1 && y <= HW && x >= 1 && x <= HW)
      v = X[plane*(HW*HW) + (y-1)*HW + (x-1)];
    Xp[idx] = v;
  }
}

// implicit-GEMM conv3x3 + BN(scale,bias) + ReLU.  Xp: (B,512,50,50), Wt: [ic][kk][oc]
__global__ __launch_bounds__(256) void conv3x3_kernel(
    const float* __restrict__ Xp, const float* __restrict__ Wt,
    const float* __restrict__ scale, const float* __restrict__ bias,
    float* __restrict__ Y)
{
  __shared__ float As[9][132];
  __shared__ float Bs[9][132];
  __shared__ int sy[128], sx[128];
  const int b  = blockIdx.z;
  const int oc0 = blockIdx.y * 128;
  const int n0  = blockIdx.x * 128;
  const int tid = threadIdx.x;
  if (tid < 128){ int n = n0 + tid; sy[tid] = n / HW; sx[tid] = n - (n/HW)*HW; }
  const int tr = (tid >> 4) * 8;
  const int tc = (tid & 15) * 8;
  float acc[8][8];
  #pragma unroll
  for (int i=0;i<8;i++)
    #pragma unroll
    for (int j=0;j<8;j++) acc[i][j]=0.f;
  const float* xpb = Xp + (long)b*CCH*PADW*PADW;
  __syncthreads();

  for (int ic = 0; ic < CCH; ic++){
    for (int idx = tid; idx < 9*128; idx += 256){
      int kk = idx >> 7, oc = idx & 127;
      As[kk][oc] = Wt[(long)ic*9*CCH + kk*CCH + oc0 + oc];
    }
    const float* xpc = xpb + (long)ic*PADW*PADW;
    for (int idx = tid; idx < 9*128; idx += 256){
      int kk = idx >> 7, j = idx & 127;
      int dy = kk/3, dx = kk - (kk/3)*3;
      Bs[kk][j] = xpc[(sy[j]+dy)*PADW + sx[j]+dx];
    }
    __syncthreads();
    #pragma unroll
    for (int kk = 0; kk < 9; kk++){
      float a[8], bb[8];
      #pragma unroll
      for (int i=0;i<8;i++) a[i]  = As[kk][tr+i];
      #pragma unroll
      for (int j=0;j<8;j++) bb[j] = Bs[kk][tc+j];
      #pragma unroll
      for (int i=0;i<8;i++)
        #pragma unroll
        for (int j=0;j<8;j++) acc[i][j] += a[i]*bb[j];
    }
    __syncthreads();
  }
  #pragma unroll
  for (int i=0;i<8;i++){
    int oc = oc0 + tr + i;
    float sc = scale[oc], bi = bias[oc];
    #pragma unroll
    for (int j=0;j<8;j++){
      int n = n0 + tc + j;
      Y[(long)b*CCH*NPIX + (long)oc*NPIX + n] = fmaxf(acc[i][j]*sc + bi, 0.f);
    }
  }
}

// ---------------- host side ----------------
template<int MODE, int EPI>
static void rungemm(const float* A, long sA, const float* B, long sB, float* C, long sC,
                    int M, int N, int K,
                    const float* p0, const float* p1,
                    const float* res, long sRes, const float* gamma)
{
  dim3 grid(N/128, (M+127)/128, NB);
  gemm_kernel<MODE,EPI><<<grid, 256>>>(A, sA, B, sB, C, sC, M, N, K, p0, p1, res, sRes, gamma);
}

static float* sym(const void* s){
  void* p = nullptr;
  cudaGetSymbolAddress(&p, s);
  return (float*)p;
}

extern "C" void kernel_launch(void* const* d_in, const int* in_sizes, int n_in,
                              void* d_out, int out_size)
{
  const float* x       = (const float*)d_in[0];
  const float* wq      = (const float*)d_in[1];
  const float* bq      = (const float*)d_in[2];
  const float* wk      = (const float*)d_in[3];
  const float* bk      = (const float*)d_in[4];
  const float* wv0     = (const float*)d_in[5];
  const float* bv0     = (const float*)d_in[6];
  const float* conv1_w = (const float*)d_in[7];
  const float* conv1_s = (const float*)d_in[8];
  const float* conv1_b = (const float*)d_in[9];
  const float* conv2_w = (const float*)d_in[10];
  const float* conv2_s = (const float*)d_in[11];
  const float* conv2_b = (const float*)d_in[12];
  const float* gamma   = (const float*)d_in[13];
  const float* gamma1  = (const float*)d_in[14];
  const float* gamma2  = (const float*)d_in[15];
  const float* c1_qw   = (const float*)d_in[16];
  const float* c1_qs   = (const float*)d_in[17];
  const float* c1_qb   = (const float*)d_in[18];
  const float* c1_ew   = (const float*)d_in[19];
  const float* c1_eb   = (const float*)d_in[20];
  const float* c2_qw   = (const float*)d_in[21];
  const float* c2_qs   = (const float*)d_in[22];
  const float* c2_qb   = (const float*)d_in[23];
  const float* c2_ew   = (const float*)d_in[24];
  const float* c2_eb   = (const float*)d_in[25];
  const float* mask1   = (const float*)d_in[26];
  const float* mask2   = (const float*)d_in[27];

  float* q    = sym(g_q);     float* k    = sym(g_k);     float* v     = sym(g_v);
  float* E    = sym(g_E);     float* A    = sym(g_A);     float* st    = sym(g_stats);
  float* buf0 = sym(g_buf0);  float* buf1 = sym(g_buf1);  float* out1  = sym(g_out1);
  float* vchl = sym(g_vchl);  float* pad  = sym(g_pad);   float* qc    = sym(g_qc);
  float* E2   = sym(g_E2);    float* expd = sym(g_expand);float* attnc = sym(g_attnc);
  float* wt1  = sym(g_wt1);   float* wt2  = sym(g_wt2);
  float* out  = (float*)d_out;

  const long sX = (long)CCH*NPIX;          // 512*2304
  const long sQ = (long)CR*NPIX;
  const long sE = (long)NPIX*NPIX;
  const long sQC = (long)CH4*NPIX;
  const long sE2 = (long)CH4*CCH;
  const long sCC = (long)CCH*CCH;
  const int  R  = NB*NPIX;
  const long total4 = (long)NB*NPIX*NPIX/4;
  const int  amg = (int)((total4 + 255)/256);

  // conv weight transposes
  wtrans_kernel<<<(CCH*CCH*9 + 255)/256, 256>>>(conv1_w, wt1);
  wtrans_kernel<<<(CCH*CCH*9 + 255)/256, 256>>>(conv2_w, wt2);

  // Q, K, V (1x1 convs)
  rungemm<0,0>(wq, 0, x, sX, q, sQ, CR,  NPIX, CCH, bq,  nullptr, nullptr, 0, nullptr);
  rungemm<0,0>(wk, 0, x, sX, k, sQ, CR,  NPIX, CCH, bk,  nullptr, nullptr, 0, nullptr);
  rungemm<0,0>(wv0,0, x, sX, v, sX, CCH, NPIX, CCH, bv0, nullptr, nullptr, 0, nullptr);

  // energy = Q^T K
  rungemm<1,0>(q, sQ, k, sQ, E, sE, NPIX, NPIX, CR, nullptr, nullptr, nullptr, 0, nullptr);

  // softmax stats for all 3 variants
  softmax_stats_kernel<<<R, 256>>>(E, mask1, mask2, st);

  // ---- pass 0 (unmasked) ----
  attn_mat_kernel<<<amg, 256>>>(E, nullptr, st, A, total4);
  rungemm<2,2>(v, sX, A, sE, buf1, sX, CCH, NPIX, NPIX, nullptr, nullptr, x, sX, gamma);
  pad_kernel<<<20000, 256>>>(buf1, pad);
  conv3x3_kernel<<<dim3(NPIX/128, CCH/128, NB), 256>>>(pad, wt1, conv1_s, conv1_b, buf0);

  // chl #1 on out0
  rungemm<0,1>(c1_qw, 0, buf0, sX, qc, sQC, CH4, NPIX, CCH, c1_qs, c1_qb, nullptr, 0, nullptr);
  rungemm<2,0>(qc, sQC, buf0, sX, E2, sE2, CH4, CCH, NPIX, nullptr, nullptr, nullptr, 0, nullptr);
  rungemm<0,0>(c1_ew, 0, E2, sE2, expd, sCC, CCH, CCH, CH4, c1_eb, nullptr, nullptr, 0, nullptr);
  chl_softmax_kernel<<<NB*CCH, 256>>>(expd, attnc);
  rungemm<0,0>(attnc, sCC, buf0, sX, vchl, sX, CCH, NPIX, CCH, nullptr, nullptr, nullptr, 0, nullptr);

  // ---- pass 1 (mask1) ----
  attn_mat_kernel<<<amg, 256>>>(E, mask1, st + 2*R, A, total4);
  rungemm<2,2>(vchl, sX, A, sE, buf1, sX, CCH, NPIX, NPIX, nullptr, nullptr, buf0, sX, gamma1);
  pad_kernel<<<20000, 256>>>(buf1, pad);
  conv3x3_kernel<<<dim3(NPIX/128, CCH/128, NB), 256>>>(pad, wt2, conv2_s, conv2_b, out1);

  // chl #2 on out1
  rungemm<0,1>(c2_qw, 0, out1, sX, qc, sQC, CH4, NPIX, CCH, c2_qs, c2_qb, nullptr, 0, nullptr);
  rungemm<2,0>(qc, sQC, out1, sX, E2, sE2, CH4, CCH, NPIX, nullptr, nullptr, nullptr, 0, nullptr);
  rungemm<0,0>(c2_ew, 0, E2, sE2, expd, sCC, CCH, CCH, CH4, c2_eb, nullptr, nullptr, 0, nullptr);
  chl_softmax_kernel<<<NB*CCH, 256>>>(expd, attnc);
  rungemm<0,0>(attnc, sCC, out1, sX, vchl, sX, CCH, NPIX, CCH, nullptr, nullptr, nullptr, 0, nullptr);

  // ---- pass 2 (mask2) -> final output ----
  attn_mat_kernel<<<amg, 256>>>(E, mask2, st + 4*R, A, total4);
  rungemm<2,2>(vchl, sX, A, sE, out, sX, CCH, NPIX, NPIX, nullptr, nullptr, out1, sX, gamma2);

  (void)in_sizes; (void)n_in; (void)out_size;
}

// round 3
// speedup vs baseline: 1.2782x; 1.2782x over previous
#include <cuda_runtime.h>
#include <cstdint>

#define NB   4
#define CCH  512
#define NPIX 2304
#define CR   64
#define CH4  128
#define HW   48
#define KCONV 4608   // 512*9

// ---------------- scratch (device globals; no dynamic allocation) ----------------
__device__ float g_q[NB*CR*NPIX];
__device__ float g_k[NB*CR*NPIX];
__device__ float g_v[NB*CCH*NPIX];
__device__ float g_E[(size_t)NB*NPIX*NPIX];      // energy
__device__ float g_A[(size_t)NB*NPIX*NPIX];      // materialized attention (reused per pass)
__device__ float g_stats[6*NB*NPIX];             // [variant][max|invsum][B*N]
__device__ float g_buf0[NB*CCH*NPIX];            // out0 (post conv1)
__device__ float g_buf1[NB*CCH*NPIX];            // pre-conv temp
__device__ float g_out1[NB*CCH*NPIX];            // out1 (post conv2)
__device__ float g_vchl[NB*CCH*NPIX];            // chl output (v1 / v2)
__device__ float g_qc[NB*CH4*NPIX];
__device__ float g_E2[NB*CH4*CCH];
__device__ float g_expand[NB*CCH*CCH];
__device__ float g_attnc[NB*CCH*CCH];
__device__ float g_cols[(size_t)NB*KCONV*NPIX];  // im2col buffer (~170MB)

// ---------------- reductions ----------------
__device__ __forceinline__ float warpMax(float v){
  #pragma unroll
  for (int o=16;o;o>>=1) v = fmaxf(v, __shfl_xor_sync(0xffffffffu, v, o));
  return v;
}
__device__ __forceinline__ float warpMin(float v){
  #pragma unroll
  for (int o=16;o;o>>=1) v = fminf(v, __shfl_xor_sync(0xffffffffu, v, o));
  return v;
}
__device__ __forceinline__ float warpSum(float v){
  #pragma unroll
  for (int o=16;o;o>>=1) v += __shfl_xor_sync(0xffffffffu, v, o);
  return v;
}
__device__ float blockMax(float v, float* sh){
  v = warpMax(v);
  if ((threadIdx.x & 31) == 0) sh[threadIdx.x >> 5] = v;
  __syncthreads();
  if (threadIdx.x < 32){
    float t = (threadIdx.x < (blockDim.x>>5)) ? sh[threadIdx.x] : -3.4e38f;
    t = warpMax(t);
    if (threadIdx.x == 0) sh[0] = t;
  }
  __syncthreads();
  float r = sh[0];
  __syncthreads();
  return r;
}
__device__ float blockMin(float v, float* sh){
  v = warpMin(v);
  if ((threadIdx.x & 31) == 0) sh[threadIdx.x >> 5] = v;
  __syncthreads();
  if (threadIdx.x < 32){
    float t = (threadIdx.x < (blockDim.x>>5)) ? sh[threadIdx.x] : 3.4e38f;
    t = warpMin(t);
    if (threadIdx.x == 0) sh[0] = t;
  }
  __syncthreads();
  float r = sh[0];
  __syncthreads();
  return r;
}
__device__ float blockSum(float v, float* sh){
  v = warpSum(v);
  if ((threadIdx.x & 31) == 0) sh[threadIdx.x >> 5] = v;
  __syncthreads();
  if (threadIdx.x < 32){
    float t = (threadIdx.x < (blockDim.x>>5)) ? sh[threadIdx.x] : 0.f;
    t = warpSum(t);
    if (threadIdx.x == 0) sh[0] = t;
  }
  __syncthreads();
  float r = sh[0];
  __syncthreads();
  return r;
}

// ---------------- tf32 helpers ----------------
__device__ __forceinline__ uint32_t f2tf(float v){
  uint32_t r; asm("cvt.rna.tf32.f32 %0, %1;" : "=r"(r) : "f"(v)); return r;
}
__device__ __forceinline__ void mma_tf32(float* c, const uint32_t* a, const uint32_t* b){
  asm volatile("mma.sync.aligned.m16n8k8.row.col.f32.tf32.tf32.f32 "
    "{%0,%1,%2,%3}, {%4,%5,%6,%7}, {%8,%9}, {%0,%1,%2,%3};\n"
    : "+f"(c[0]), "+f"(c[1]), "+f"(c[2]), "+f"(c[3])
    : "r"(a[0]), "r"(a[1]), "r"(a[2]), "r"(a[3]), "r"(b[0]), "r"(b[1]));
}

// ---------------- TF32 tensor-core GEMM (3xTF32 emulated-fp32) ----------------
// MODE 0 = NN (A: MxK, B: KxN), 1 = TN (A: KxM, B: KxN), 2 = NT (A: MxK, B: NxK)
// EPI  0 = optional per-row bias p0; 1 = relu(acc*p0[m]+p1[m]); 2 = gamma[0]*acc + res[m,n]
// SPLIT=1 -> hi/lo split, 3 mmas per k-step (~fp32 accuracy), K-tile 16.
// Requirements: N % 128 == 0, K % KT == 0. M guarded.
template<int MODE, int EPI, int SPLIT>
__global__ __launch_bounds__(256) void gemm_tf32_kernel(
    const float* __restrict__ A, long sA,
    const float* __restrict__ Bm, long sB,
    float* __restrict__ Cm, long sC,
    int M, int N, int K,
    const float* __restrict__ p0, const float* __restrict__ p1,
    const float* __restrict__ res, long sRes,
    const float* __restrict__ gamma)
{
  constexpr int KT = SPLIT ? 16 : 32;
  const int b = blockIdx.z;
  A  += (long)b * sA;
  Bm += (long)b * sB;
  Cm += (long)b * sC;
  if (EPI == 2) res += (long)b * sRes;

  __shared__ uint32_t As[32][136];   // rows [0,KT) hi, [KT,2KT) lo (when SPLIT)
  __shared__ uint32_t Bs[32][136];

  const int tid  = threadIdx.x;
  const int warp = tid >> 5;
  const int lane = tid & 31;
  const int g    = lane >> 2;
  const int ct   = lane & 3;
  const int warpM = warp >> 2;       // 0..1
  const int warpN = warp & 3;        // 0..3
  const int m0 = blockIdx.y * 128;
  const int n0 = blockIdx.x * 128;

  float acc[4][4][4];
  #pragma unroll
  for (int i=0;i<4;i++)
    #pragma unroll
    for (int j=0;j<4;j++)
      #pragma unroll
      for (int c=0;c<4;c++) acc[i][j][c]=0.f;

  for (int k0 = 0; k0 < K; k0 += KT){
    // ---- A tile -> As[k][m]
    if (MODE == 0 || MODE == 2){
      const int arow  = tid >> 1;
      const int acol0 = (tid & 1) * (KT/2);
      const int m = m0 + arow;
      #pragma unroll
      for (int c4 = 0; c4 < KT/8; c4++){
        int kc = acol0 + c4*4;
        float4 v = make_float4(0.f,0.f,0.f,0.f);
        if (m < M) v = *(const float4*)&A[(long)m * K + k0 + kc];
        uint32_t h0=f2tf(v.x), h1=f2tf(v.y), h2=f2tf(v.z), h3=f2tf(v.w);
        As[kc+0][arow]=h0; As[kc+1][arow]=h1; As[kc+2][arow]=h2; As[kc+3][arow]=h3;
        if (SPLIT){
          As[KT+kc+0][arow]=f2tf(v.x-__uint_as_float(h0));
          As[KT+kc+1][arow]=f2tf(v.y-__uint_as_float(h1));
          As[KT+kc+2][arow]=f2tf(v.z-__uint_as_float(h2));
          As[KT+kc+3][arow]=f2tf(v.w-__uint_as_float(h3));
        }
      }
    } else { // MODE 1: A is K x M
      constexpr int tpk = 256/KT;
      const int ak  = tid / tpk;
      const int am0 = (tid % tpk) * (128/tpk);
      #pragma unroll
      for (int c4 = 0; c4 < (128/tpk)/4; c4++){
        int am = am0 + c4*4;
        float4 v = make_float4(0.f,0.f,0.f,0.f);
        if (m0 + am < M) v = *(const float4*)&A[(long)(k0+ak)*M + m0 + am];
        uint32_t h0=f2tf(v.x), h1=f2tf(v.y), h2=f2tf(v.z), h3=f2tf(v.w);
        As[ak][am+0]=h0; As[ak][am+1]=h1; As[ak][am+2]=h2; As[ak][am+3]=h3;
        if (SPLIT){
          As[KT+ak][am+0]=f2tf(v.x-__uint_as_float(h0));
          As[KT+ak][am+1]=f2tf(v.y-__uint_as_float(h1));
          As[KT+ak][am+2]=f2tf(v.z-__uint_as_float(h2));
          As[KT+ak][am+3]=f2tf(v.w-__uint_as_float(h3));
        }
      }
    }
    // ---- B tile -> Bs[k][n]
    if (MODE == 0 || MODE == 1){ // B is K x N
      constexpr int tpk = 256/KT;
      const int bk  = tid / tpk;
      const int bn0 = (tid % tpk) * (128/tpk);
      #pragma unroll
      for (int c4 = 0; c4 < (128/tpk)/4; c4++){
        int bn = bn0 + c4*4;
        float4 v = *(const float4*)&Bm[(long)(k0+bk)*N + n0 + bn];
        uint32_t h0=f2tf(v.x), h1=f2tf(v.y), h2=f2tf(v.z), h3=f2tf(v.w);
        Bs[bk][bn+0]=h0; Bs[bk][bn+1]=h1; Bs[bk][bn+2]=h2; Bs[bk][bn+3]=h3;
        if (SPLIT){
          Bs[KT+bk][bn+0]=f2tf(v.x-__uint_as_float(h0));
          Bs[KT+bk][bn+1]=f2tf(v.y-__uint_as_float(h1));
          Bs[KT+bk][bn+2]=f2tf(v.z-__uint_as_float(h2));
          Bs[KT+bk][bn+3]=f2tf(v.w-__uint_as_float(h3));
        }
      }
    } else { // MODE 2: B is N x K
      const int brow  = tid >> 1;
      const int bcol0 = (tid & 1) * (KT/2);
      #pragma unroll
      for (int c4 = 0; c4 < KT/8; c4++){
        int kc = bcol0 + c4*4;
        float4 v = *(const float4*)&Bm[(long)(n0+brow)*K + k0 + kc];
        uint32_t h0=f2tf(v.x), h1=f2tf(v.y), h2=f2tf(v.z), h3=f2tf(v.w);
        Bs[kc+0][brow]=h0; Bs[kc+1][brow]=h1; Bs[kc+2][brow]=h2; Bs[kc+3][brow]=h3;
        if (SPLIT){
          Bs[KT+kc+0][brow]=f2tf(v.x-__uint_as_float(h0));
          Bs[KT+kc+1][brow]=f2tf(v.y-__uint_as_float(h1));
          Bs[KT+kc+2][brow]=f2tf(v.z-__uint_as_float(h2));
          Bs[KT+kc+3][brow]=f2tf(v.w-__uint_as_float(h3));
        }
      }
    }
    __syncthreads();

    #pragma unroll
    for (int kk = 0; kk < KT/8; kk++){
      const int kb = kk*8;
      uint32_t a[4][4], bf[4][2];
      #pragma unroll
      for (int mi=0; mi<4; mi++){
        int r = warpM*64 + mi*16 + g;
        a[mi][0] = As[kb+ct  ][r];
        a[mi][1] = As[kb+ct  ][r+8];
        a[mi][2] = As[kb+ct+4][r];
        a[mi][3] = As[kb+ct+4][r+8];
      }
      #pragma unroll
      for (int nj=0; nj<4; nj++){
        int cl = warpN*32 + nj*8 + g;
        bf[nj][0] = Bs[kb+ct  ][cl];
        bf[nj][1] = Bs[kb+ct+4][cl];
      }
      #pragma unroll
      for (int mi=0; mi<4; mi++)
        #pragma unroll
        for (int nj=0; nj<4; nj++) mma_tf32(acc[mi][nj], a[mi], bf[nj]);

      if (SPLIT){
        uint32_t al[4][4], bl[4][2];
        #pragma unroll
        for (int mi=0; mi<4; mi++){
          int r = warpM*64 + mi*16 + g;
          al[mi][0] = As[KT+kb+ct  ][r];
          al[mi][1] = As[KT+kb+ct  ][r+8];
          al[mi][2] = As[KT+kb+ct+4][r];
          al[mi][3] = As[KT+kb+ct+4][r+8];
        }
        #pragma unroll
        for (int nj=0; nj<4; nj++){
          int cl = warpN*32 + nj*8 + g;
          bl[nj][0] = Bs[KT+kb+ct  ][cl];
          bl[nj][1] = Bs[KT+kb+ct+4][cl];
        }
        #pragma unroll
        for (int mi=0; mi<4; mi++)
          #pragma unroll
          for (int nj=0; nj<4; nj++){
            mma_tf32(acc[mi][nj], al[mi], bf[nj]);
            mma_tf32(acc[mi][nj], a[mi],  bl[nj]);
          }
      }
    }
    __syncthreads();
  }

  // ---- epilogue
  #pragma unroll
  for (int mi=0; mi<4; mi++){
    int r0 = m0 + warpM*64 + mi*16 + g;
    int r1 = r0 + 8;
    float s0=0.f, o0=0.f, s1=0.f, o1=0.f;
    if (EPI == 1){
      if (r0 < M){ s0 = p0[r0]; o0 = p1[r0]; }
      if (r1 < M){ s1 = p0[r1]; o1 = p1[r1]; }
    } else if (EPI == 0){
      if (p0){ if (r0 < M) o0 = p0[r0]; if (r1 < M) o1 = p0[r1]; }
    }
    #pragma unroll
    for (int nj=0; nj<4; nj++){
      int n = n0 + warpN*32 + nj*8 + 2*ct;
      if (r0 < M){
        float2 w;
        if (EPI == 0){ w.x = acc[mi][nj][0] + o0; w.y = acc[mi][nj][1] + o0; }
        else if (EPI == 1){
          w.x = fmaxf(acc[mi][nj][0]*s0 + o0, 0.f);
          w.y = fmaxf(acc[mi][nj][1]*s0 + o0, 0.f);
        } else {
          float2 rr = *(const float2*)&res[(long)r0*N + n];
          w.x = gamma[0]*acc[mi][nj][0] + rr.x;
          w.y = gamma[0]*acc[mi][nj][1] + rr.y;
        }
        *(float2*)&Cm[(long)r0*N + n] = w;
      }
      if (r1 < M){
        float2 w;
        if (EPI == 0){ w.x = acc[mi][nj][2] + o1; w.y = acc[mi][nj][3] + o1; }
        else if (EPI == 1){
          w.x = fmaxf(acc[mi][nj][2]*s1 + o1, 0.f);
          w.y = fmaxf(acc[mi][nj][3]*s1 + o1, 0.f);
        } else {
          float2 rr = *(const float2*)&res[(long)r1*N + n];
          w.x = gamma[0]*acc[mi][nj][2] + rr.x;
          w.y = gamma[0]*acc[mi][nj][3] + rr.y;
        }
        *(float2*)&Cm[(long)r1*N + n] = w;
      }
    }
  }
}

// ---------------- softmax row stats (3 variants, one pass) ----------------
__global__ __launch_bounds__(256) void softmax_stats_kernel(
    const float* __restrict__ E, const float* __restrict__ M1,
    const float* __restrict__ M2, float* __restrict__ st)
{
  __shared__ float sh[32];
  const int R = NB*NPIX;
  int row = blockIdx.x;            // b*N + m
  int mr  = row % NPIX;
  const float* e  = E  + (long)row * NPIX;
  const float* m1 = M1 + (long)mr  * NPIX;
  const float* m2 = M2 + (long)mr  * NPIX;
  int tid = threadIdx.x;

  float ev[9], w1[9], w2[9];
  float mx0=-3.4e38f, mx1=-3.4e38f, mx2=-3.4e38f;
  #pragma unroll
  for (int i=0;i<9;i++){
    int n = tid + i*256;
    ev[i]=e[n]; w1[i]=m1[n]; w2[i]=m2[n];
    mx0 = fmaxf(mx0, ev[i]);
    if (w1[i] > 0.f) mx1 = fmaxf(mx1, ev[i]);
    if (w2[i] > 0.f) mx2 = fmaxf(mx2, ev[i]);
  }
  mx0 = blockMax(mx0, sh);
  mx1 = blockMax(mx1, sh);
  mx2 = blockMax(mx2, sh);
  float s0=0.f, s1=0.f, s2=0.f;
  #pragma unroll
  for (int i=0;i<9;i++){
    s0 += __expf(ev[i]-mx0);
    s1 += (w1[i] > 0.f) ? __expf(ev[i]-mx1) : 0.f;
    s2 += (w2[i] > 0.f) ? __expf(ev[i]-mx2) : 0.f;
  }
  s0 = blockSum(s0, sh);
  s1 = blockSum(s1, sh);
  s2 = blockSum(s2, sh);
  if (tid == 0){
    st[row]       = mx0;  st[R   + row] = 1.f/s0;
    st[2*R + row] = mx1;  st[3*R + row] = 1.f/s1;
    st[4*R + row] = mx2;  st[5*R + row] = 1.f/s2;
  }
}

// ---------------- materialize attention matrix ----------------
__global__ __launch_bounds__(256) void attn_mat_kernel(
    const float* __restrict__ E, const float* __restrict__ mask,
    const float* __restrict__ st, float* __restrict__ A, long total4)
{
  const long NN2 = (long)NPIX*NPIX;
  long i4 = (long)blockIdx.x * 256 + threadIdx.x;
  if (i4 >= total4) return;
  long idx = i4 * 4;
  int  b   = (int)(idx / NN2);
  long rem = idx - (long)b * NN2;
  int  mr  = (int)(rem / NPIX);
  float mx   = st[b*NPIX + mr];
  float rinv = st[NB*NPIX + b*NPIX + mr];
  float4 e = *(const float4*)&E[idx];
  float4 a;
  a.x = __expf(e.x-mx)*rinv;
  a.y = __expf(e.y-mx)*rinv;
  a.z = __expf(e.z-mx)*rinv;
  a.w = __expf(e.w-mx)*rinv;
  if (mask){
    float4 mk = *(const float4*)&mask[rem];
    if (mk.x <= 0.f) a.x = 0.f;
    if (mk.y <= 0.f) a.y = 0.f;
    if (mk.z <= 0.f) a.z = 0.f;
    if (mk.w <= 0.f) a.w = 0.f;
  }
  *(float4*)&A[idx] = a;
}

// ---------------- chl softmax: attn[o,c] = softmax_c(rowmax - expand[o,c]) ----------------
__global__ __launch_bounds__(256) void chl_softmax_kernel(
    const float* __restrict__ E, float* __restrict__ A)
{
  __shared__ float sh[32];
  long row = blockIdx.x;
  const float* e = E + row * CCH;
  float* a = A + row * CCH;
  int tid = threadIdx.x;
  float v0 = e[tid], v1 = e[tid+256];
  float mn = blockMin(fminf(v0, v1), sh);   // softmax(max-e) == exp(mn-e)/sum
  float t0 = __expf(mn - v0), t1 = __expf(mn - v1);
  float s = blockSum(t0 + t1, sh);
  float rinv = 1.f/s;
  a[tid]     = t0*rinv;
  a[tid+256] = t1*rinv;
}

// ---------------- im2col: X (B,512,48,48) -> Cols (B,4608,2304), SAME pad ----------------
__global__ __launch_bounds__(256) void im2col_kernel(const float* __restrict__ X,
                                                     float* __restrict__ Cols)
{
  long idx = (long)blockIdx.x * 256 + threadIdx.x;
  const long total = (long)NB*KCONV*NPIX;
  if (idx >= total) return;
  int n = (int)(idx % NPIX);
  long t = idx / NPIX;
  int kk = (int)(t % 9);
  long t2 = t / 9;
  int ic = (int)(t2 % CCH);
  int b  = (int)(t2 / CCH);
  int y = n / HW, x = n - y*HW;
  int ky = kk / 3, kx = kk - ky*3;
  int sy = y + ky - 1, sx = x + kx - 1;
  float v = 0.f;
  if (sy >= 0 && sy < HW && sx >= 0 && sx < HW)
    v = X[((long)(b*CCH + ic))*NPIX + sy*HW + sx];
  Cols[idx] = v;
}

// ---------------- host side ----------------
template<int MODE, int EPI, int SPLIT>
static void rungemm(const float* A, long sA, const float* B, long sB, float* C, long sC,
                    int M, int N, int K,
                    const float* p0, const float* p1,
                    const float* res, long sRes, const float* gamma)
{
  dim3 grid(N/128, (M+127)/128, NB);
  gemm_tf32_kernel<MODE,EPI,SPLIT><<<grid, 256>>>(A, sA, B, sB, C, sC, M, N, K,
                                                  p0, p1, res, sRes, gamma);
}

static float* sym(const void* s){
  void* p = nullptr;
  cudaGetSymbolAddress(&p, s);
  return (float*)p;
}

extern "C" void kernel_launch(void* const* d_in, const int* in_sizes, int n_in,
                              void* d_out, int out_size)
{
  const float* x       = (const float*)d_in[0];
  const float* wq      = (const float*)d_in[1];
  const float* bq      = (const float*)d_in[2];
  const float* wk      = (const float*)d_in[3];
  const float* bk      = (const float*)d_in[4];
  const float* wv0     = (const float*)d_in[5];
  const float* bv0     = (const float*)d_in[6];
  const float* conv1_w = (const float*)d_in[7];
  const float* conv1_s = (const float*)d_in[8];
  const float* conv1_b = (const float*)d_in[9];
  const float* conv2_w = (const float*)d_in[10];
  const float* conv2_s = (const float*)d_in[11];
  const float* conv2_b = (const float*)d_in[12];
  const float* gamma   = (const float*)d_in[13];
  const float* gamma1  = (const float*)d_in[14];
  const float* gamma2  = (const float*)d_in[15];
  const float* c1_qw   = (const float*)d_in[16];
  const float* c1_qs   = (const float*)d_in[17];
  const float* c1_qb   = (const float*)d_in[18];
  const float* c1_ew   = (const float*)d_in[19];
  const float* c1_eb   = (const float*)d_in[20];
  const float* c2_qw   = (const float*)d_in[21];
  const float* c2_qs   = (const float*)d_in[22];
  const float* c2_qb   = (const float*)d_in[23];
  const float* c2_ew   = (const float*)d_in[24];
  const float* c2_eb   = (const float*)d_in[25];
  const float* mask1   = (const float*)d_in[26];
  const float* mask2   = (const float*)d_in[27];

  float* q    = sym(g_q);     float* k    = sym(g_k);     float* v     = sym(g_v);
  float* E    = sym(g_E);     float* A    = sym(g_A);     float* st    = sym(g_stats);
  float* buf0 = sym(g_buf0);  float* buf1 = sym(g_buf1);  float* out1  = sym(g_out1);
  float* vchl = sym(g_vchl);  float* qc   = sym(g_qc);    float* E2    = sym(g_E2);
  float* expd = sym(g_expand);float* attnc= sym(g_attnc); float* cols  = sym(g_cols);
  float* out  = (float*)d_out;

  const long sX  = (long)CCH*NPIX;
  const long sQ  = (long)CR*NPIX;
  const long sE  = (long)NPIX*NPIX;
  const long sQC = (long)CH4*NPIX;
  const long sE2 = (long)CH4*CCH;
  const long sCC = (long)CCH*CCH;
  const long sCOL= (long)KCONV*NPIX;
  const int  R   = NB*NPIX;
  const long total4 = (long)NB*NPIX*NPIX/4;
  const int  amg = (int)((total4 + 255)/256);
  const long colTotal = (long)NB*KCONV*NPIX;
  const int  colg = (int)((colTotal + 255)/256);

  // Q, K, V (1x1 convs)  — all 3xTF32
  rungemm<0,0,1>(wq, 0, x, sX, q, sQ, CR,  NPIX, CCH, bq,  nullptr, nullptr, 0, nullptr);
  rungemm<0,0,1>(wk, 0, x, sX, k, sQ, CR,  NPIX, CCH, bk,  nullptr, nullptr, 0, nullptr);
  rungemm<0,0,1>(wv0,0, x, sX, v, sX, CCH, NPIX, CCH, bv0, nullptr, nullptr, 0, nullptr);

  // energy = Q^T K
  rungemm<1,0,1>(q, sQ, k, sQ, E, sE, NPIX, NPIX, CR, nullptr, nullptr, nullptr, 0, nullptr);

  // softmax stats for all 3 variants
  softmax_stats_kernel<<<R, 256>>>(E, mask1, mask2, st);

  // ---- pass 0 (unmasked) ----
  attn_mat_kernel<<<amg, 256>>>(E, nullptr, st, A, total4);
  rungemm<2,2,1>(v, sX, A, sE, buf1, sX, CCH, NPIX, NPIX, nullptr, nullptr, x, sX, gamma);
  im2col_kernel<<<colg, 256>>>(buf1, cols);
  rungemm<0,1,1>(conv1_w, 0, cols, sCOL, buf0, sX, CCH, NPIX, KCONV, conv1_s, conv1_b, nullptr, 0, nullptr);

  // chl #1 on out0
  rungemm<0,1,1>(c1_qw, 0, buf0, sX, qc, sQC, CH4, NPIX, CCH, c1_qs, c1_qb, nullptr, 0, nullptr);
  rungemm<2,0,1>(qc, sQC, buf0, sX, E2, sE2, CH4, CCH, NPIX, nullptr, nullptr, nullptr, 0, nullptr);
  rungemm<0,0,1>(c1_ew, 0, E2, sE2, expd, sCC, CCH, CCH, CH4, c1_eb, nullptr, nullptr, 0, nullptr);
  chl_softmax_kernel<<<NB*CCH, 256>>>(expd, attnc);
  rungemm<0,0,1>(attnc, sCC, buf0, sX, vchl, sX, CCH, NPIX, CCH, nullptr, nullptr, nullptr, 0, nullptr);

  // ---- pass 1 (mask1) ----
  attn_mat_kernel<<<amg, 256>>>(E, mask1, st + 2*R, A, total4);
  rungemm<2,2,1>(vchl, sX, A, sE, buf1, sX, CCH, NPIX, NPIX, nullptr, nullptr, buf0, sX, gamma1);
  im2col_kernel<<<colg, 256>>>(buf1, cols);
  rungemm<0,1,1>(conv2_w, 0, cols, sCOL, out1, sX, CCH, NPIX, KCONV, conv2_s, conv2_b, nullptr, 0, nullptr);

  // chl #2 on out1
  rungemm<0,1,1>(c2_qw, 0, out1, sX, qc, sQC, CH4, NPIX, CCH, c2_qs, c2_qb, nullptr, 0, nullptr);
  rungemm<2,0,1>(qc, sQC, out1, sX, E2, sE2, CH4, CCH, NPIX, nullptr, nullptr, nullptr, 0, nullptr);
  rungemm<0,0,1>(c2_ew, 0, E2, sE2, expd, sCC, CCH, CCH, CH4, c2_eb, nullptr, nullptr, 0, nullptr);
  chl_softmax_kernel<<<NB*CCH, 256>>>(expd, attnc);
  rungemm<0,0,1>(attnc, sCC, out1, sX, vchl, sX, CCH, NPIX, CCH, nullptr, nullptr, nullptr, 0, nullptr);

  // ---- pass 2 (mask2) -> final output ----
  attn_mat_kernel<<<amg, 256>>>(E, mask2, st + 4*R, A, total4);
  rungemm<2,2,1>(vchl, sX, A, sE, out, sX, CCH, NPIX, NPIX, nullptr, nullptr, out1, sX, gamma2);

  (void)in_sizes; (void)n_in; (void)out_size;
}

// round 4
// speedup vs baseline: 1.9222x; 1.5039x over previous
#include <cuda_runtime.h>
#include <cstdint>

#define NB   4
#define CCH  512
#define NPIX 2304
#define CR   64
#define CH4  128
#define HW   48
#define KCONV 4608   // 512*9

// ---------------- scratch (device globals; no dynamic allocation) ----------------
__device__ float g_q[NB*CR*NPIX];
__device__ float g_k[NB*CR*NPIX];
__device__ float g_v[NB*CCH*NPIX];
__device__ float g_E[(size_t)NB*NPIX*NPIX];      // energy
__device__ float g_A[(size_t)NB*NPIX*NPIX];      // materialized attention (reused per pass)
__device__ float g_stats[6*NB*NPIX];             // [variant][max|invsum][B*N]
__device__ float g_buf0[NB*CCH*NPIX];            // out0 (post conv1)
__device__ float g_buf1[NB*CCH*NPIX];            // pre-conv temp
__device__ float g_out1[NB*CCH*NPIX];            // out1 (post conv2)
__device__ float g_vchl[NB*CCH*NPIX];            // chl output (v1 / v2)
__device__ float g_qc[NB*CH4*NPIX];
__device__ float g_E2[NB*CH4*CCH];
__device__ float g_expand[NB*CCH*CCH];
__device__ float g_attnc[NB*CCH*CCH];
__device__ float g_cols[(size_t)NB*KCONV*NPIX];  // im2col buffer (~170MB)

// ---------------- reductions ----------------
__device__ __forceinline__ float warpMax(float v){
  #pragma unroll
  for (int o=16;o;o>>=1) v = fmaxf(v, __shfl_xor_sync(0xffffffffu, v, o));
  return v;
}
__device__ __forceinline__ float warpMin(float v){
  #pragma unroll
  for (int o=16;o;o>>=1) v = fminf(v, __shfl_xor_sync(0xffffffffu, v, o));
  return v;
}
__device__ __forceinline__ float warpSum(float v){
  #pragma unroll
  for (int o=16;o;o>>=1) v += __shfl_xor_sync(0xffffffffu, v, o);
  return v;
}
__device__ float blockMax(float v, float* sh){
  v = warpMax(v);
  if ((threadIdx.x & 31) == 0) sh[threadIdx.x >> 5] = v;
  __syncthreads();
  if (threadIdx.x < 32){
    float t = (threadIdx.x < (blockDim.x>>5)) ? sh[threadIdx.x] : -3.4e38f;
    t = warpMax(t);
    if (threadIdx.x == 0) sh[0] = t;
  }
  __syncthreads();
  float r = sh[0];
  __syncthreads();
  return r;
}
__device__ float blockMin(float v, float* sh){
  v = warpMin(v);
  if ((threadIdx.x & 31) == 0) sh[threadIdx.x >> 5] = v;
  __syncthreads();
  if (threadIdx.x < 32){
    float t = (threadIdx.x < (blockDim.x>>5)) ? sh[threadIdx.x] : 3.4e38f;
    t = warpMin(t);
    if (threadIdx.x == 0) sh[0] = t;
  }
  __syncthreads();
  float r = sh[0];
  __syncthreads();
  return r;
}
__device__ float blockSum(float v, float* sh){
  v = warpSum(v);
  if ((threadIdx.x & 31) == 0) sh[threadIdx.x >> 5] = v;
  __syncthreads();
  if (threadIdx.x < 32){
    float t = (threadIdx.x < (blockDim.x>>5)) ? sh[threadIdx.x] : 0.f;
    t = warpSum(t);
    if (threadIdx.x == 0) sh[0] = t;
  }
  __syncthreads();
  float r = sh[0];
  __syncthreads();
  return r;
}

// ---------------- mma / cp.async helpers ----------------
__device__ __forceinline__ void mma_tf32(float* c, const uint32_t* a, const uint32_t* b){
  asm volatile("mma.sync.aligned.m16n8k8.row.col.f32.tf32.tf32.f32 "
    "{%0,%1,%2,%3}, {%4,%5,%6,%7}, {%8,%9}, {%0,%1,%2,%3};\n"
    : "+f"(c[0]), "+f"(c[1]), "+f"(c[2]), "+f"(c[3])
    : "r"(a[0]), "r"(a[1]), "r"(a[2]), "r"(a[3]), "r"(b[0]), "r"(b[1]));
}
__device__ __forceinline__ void cpasync16(float* dst, const float* src, int szbytes){
  uint32_t d = (uint32_t)__cvta_generic_to_shared(dst);
  asm volatile("cp.async.cg.shared.global [%0], [%1], 16, %2;\n"
               :: "r"(d), "l"(src), "r"(szbytes));
}
__device__ __forceinline__ void cp_commit(){ asm volatile("cp.async.commit_group;\n"); }
__device__ __forceinline__ void cp_wait0(){ asm volatile("cp.async.wait_group 0;\n"); }
__device__ __forceinline__ void cp_wait1(){ asm volatile("cp.async.wait_group 1;\n"); }

// split: hi = top-19-bit truncation (exactly representable in tf32); lo = f - hi.
// HMMA reads tf32 operands as the high 19 bits, so lo needs no explicit cvt.
__device__ __forceinline__ void split_hl(float f, uint32_t& hi, uint32_t& lo){
  uint32_t u = __float_as_uint(f);
  hi = u & 0xffffe000u;
  lo = __float_as_uint(f - __uint_as_float(hi));
}

// ---------------- TF32 tensor-core GEMM, cp.async double-buffered, 3xTF32 ----------------
// MODE 0 = NN (A: MxK, B: KxN), 1 = TN (A: KxM, B: KxN), 2 = NT (A: MxK, B: NxK)
// EPI  0 = optional per-row bias p0; 1 = relu(acc*p0[m]+p1[m]); 2 = gamma[0]*acc + res[m,n]
// Requirements: N % 128 == 0, K % 16 == 0, M % 4 == 0 (zero-filled above M). Block tile 128x128x16.
template<int MODE, int EPI>
__global__ void __launch_bounds__(256) gemm2_kernel(
    const float* __restrict__ A, long sA,
    const float* __restrict__ Bm, long sB,
    float* __restrict__ Cm, long sC,
    int M, int N, int K,
    const float* __restrict__ p0, const float* __restrict__ p1,
    const float* __restrict__ res, long sRes,
    const float* __restrict__ gamma)
{
  // smem layouts (padded for conflict-free fragment loads):
  //   MODE 0/2 A: [m][k]  stride 20   ;  MODE 1 A: [k][m] stride 136
  //   MODE 0/1 B: [k][n]  stride 136  ;  MODE 2 B: [n][k] stride 20
  constexpr int AST   = (MODE==1) ? 136 : 20;
  constexpr int ASIZE = (MODE==1) ? 16*136 : 128*20;
  constexpr int BST   = (MODE==2) ? 20 : 136;
  constexpr int BSIZE = (MODE==2) ? 128*20 : 16*136;

  __shared__ float As[2][ASIZE];
  __shared__ float Bs[2][BSIZE];

  const int b = blockIdx.z;
  A  += (long)b * sA;
  Bm += (long)b * sB;
  Cm += (long)b * sC;
  if (EPI == 2) res += (long)b * sRes;

  const int tid  = threadIdx.x;
  const int warp = tid >> 5;
  const int lane = tid & 31;
  const int g    = lane >> 2;
  const int ct   = lane & 3;
  const int warpM = warp >> 2;       // 0..1
  const int warpN = warp & 3;        // 0..3
  const int m0 = blockIdx.y * 128;
  const int n0 = blockIdx.x * 128;

  float acc[4][4][4];
  #pragma unroll
  for (int i=0;i<4;i++)
    #pragma unroll
    for (int j=0;j<4;j++)
      #pragma unroll
      for (int c=0;c<4;c++) acc[i][j][c]=0.f;

  // ---- tile loaders (cp.async, 2 x 16B per thread per matrix) ----
  auto loadA = [&](int stage, int k0){
    #pragma unroll
    for (int c = tid; c < 512; c += 256){
      if (MODE == 0 || MODE == 2){
        int m = c >> 2, seg = (c & 3) * 4;
        int gm = m0 + m;
        int sz = (gm < M) ? 16 : 0;
        if (gm >= M) gm = M - 1;
        cpasync16(&As[stage][m*AST + seg], A + (long)gm*K + k0 + seg, sz);
      } else {
        int k = c >> 5, seg = (c & 31) * 4;
        int gm = m0 + seg;
        int sz = (gm < M) ? 16 : 0;
        if (gm >= M) gm = 0;
        cpasync16(&As[stage][k*AST + seg], A + (long)(k0+k)*M + m0 + ((sz)?seg:0), sz);
      }
    }
  };
  auto loadB = [&](int stage, int k0){
    #pragma unroll
    for (int c = tid; c < 512; c += 256){
      if (MODE == 0 || MODE == 1){
        int k = c >> 5, seg = (c & 31) * 4;
        cpasync16(&Bs[stage][k*BST + seg], Bm + (long)(k0+k)*N + n0 + seg, 16);
      } else {
        int n = c >> 2, seg = (c & 3) * 4;
        cpasync16(&Bs[stage][n*BST + seg], Bm + (long)(n0+n)*K + k0 + seg, 16);
      }
    }
  };

  const int T = K / 16;
  loadA(0, 0); loadB(0, 0); cp_commit();

  for (int i = 0; i < T; i++){
    const int cur = i & 1;
    if (i + 1 < T){
      loadA(cur^1, (i+1)*16); loadB(cur^1, (i+1)*16); cp_commit();
      cp_wait1();
    } else {
      cp_wait0();
    }
    __syncthreads();

    #pragma unroll
    for (int kk = 0; kk < 2; kk++){
      const int kb = kk*8;
      // fragment loads (raw fp32)
      float a32[4][4], b32[4][2];
      #pragma unroll
      for (int mi=0; mi<4; mi++){
        int r = warpM*64 + mi*16 + g;
        if (MODE == 0 || MODE == 2){
          a32[mi][0] = As[cur][(r   )*AST + kb+ct  ];
          a32[mi][1] = As[cur][(r+8 )*AST + kb+ct  ];
          a32[mi][2] = As[cur][(r   )*AST + kb+ct+4];
          a32[mi][3] = As[cur][(r+8 )*AST + kb+ct+4];
        } else {
          a32[mi][0] = As[cur][(kb+ct  )*AST + r  ];
          a32[mi][1] = As[cur][(kb+ct  )*AST + r+8];
          a32[mi][2] = As[cur][(kb+ct+4)*AST + r  ];
          a32[mi][3] = As[cur][(kb+ct+4)*AST + r+8];
        }
      }
      #pragma unroll
      for (int nj=0; nj<4; nj++){
        int cl = warpN*32 + nj*8 + g;
        if (MODE == 0 || MODE == 1){
          b32[nj][0] = Bs[cur][(kb+ct  )*BST + cl];
          b32[nj][1] = Bs[cur][(kb+ct+4)*BST + cl];
        } else {
          b32[nj][0] = Bs[cur][cl*BST + kb+ct  ];
          b32[nj][1] = Bs[cur][cl*BST + kb+ct+4];
        }
      }
      // in-register hi/lo split
      uint32_t ah[4][4], al[4][4], bh[4][2], bl[4][2];
      #pragma unroll
      for (int mi=0; mi<4; mi++)
        #pragma unroll
        for (int c=0; c<4; c++) split_hl(a32[mi][c], ah[mi][c], al[mi][c]);
      #pragma unroll
      for (int nj=0; nj<4; nj++)
        #pragma unroll
        for (int c=0; c<2; c++) split_hl(b32[nj][c], bh[nj][c], bl[nj][c]);
      // 3xTF32
      #pragma unroll
      for (int mi=0; mi<4; mi++)
        #pragma unroll
        for (int nj=0; nj<4; nj++){
          mma_tf32(acc[mi][nj], ah[mi], bh[nj]);
          mma_tf32(acc[mi][nj], ah[mi], bl[nj]);
          mma_tf32(acc[mi][nj], al[mi], bh[nj]);
        }
    }
    __syncthreads();
  }

  // ---- epilogue
  #pragma unroll
  for (int mi=0; mi<4; mi++){
    int r0 = m0 + warpM*64 + mi*16 + g;
    int r1 = r0 + 8;
    float s0=0.f, o0=0.f, s1=0.f, o1=0.f;
    if (EPI == 1){
      if (r0 < M){ s0 = p0[r0]; o0 = p1[r0]; }
      if (r1 < M){ s1 = p0[r1]; o1 = p1[r1]; }
    } else if (EPI == 0){
      if (p0){ if (r0 < M) o0 = p0[r0]; if (r1 < M) o1 = p0[r1]; }
    }
    #pragma unroll
    for (int nj=0; nj<4; nj++){
      int n = n0 + warpN*32 + nj*8 + 2*ct;
      if (r0 < M){
        float2 w;
        if (EPI == 0){ w.x = acc[mi][nj][0] + o0; w.y = acc[mi][nj][1] + o0; }
        else if (EPI == 1){
          w.x = fmaxf(acc[mi][nj][0]*s0 + o0, 0.f);
          w.y = fmaxf(acc[mi][nj][1]*s0 + o0, 0.f);
        } else {
          float2 rr = *(const float2*)&res[(long)r0*N + n];
          w.x = gamma[0]*acc[mi][nj][0] + rr.x;
          w.y = gamma[0]*acc[mi][nj][1] + rr.y;
        }
        *(float2*)&Cm[(long)r0*N + n] = w;
      }
      if (r1 < M){
        float2 w;
        if (EPI == 0){ w.x = acc[mi][nj][2] + o1; w.y = acc[mi][nj][3] + o1; }
        else if (EPI == 1){
          w.x = fmaxf(acc[mi][nj][2]*s1 + o1, 0.f);
          w.y = fmaxf(acc[mi][nj][3]*s1 + o1, 0.f);
        } else {
          float2 rr = *(const float2*)&res[(long)r1*N + n];
          w.x = gamma[0]*acc[mi][nj][2] + rr.x;
          w.y = gamma[0]*acc[mi][nj][3] + rr.y;
        }
        *(float2*)&Cm[(long)r1*N + n] = w;
      }
    }
  }
}

// ---------------- softmax row stats (3 variants, one pass) ----------------
__global__ __launch_bounds__(256) void softmax_stats_kernel(
    const float* __restrict__ E, const float* __restrict__ M1,
    const float* __restrict__ M2, float* __restrict__ st)
{
  __shared__ float sh[32];
  const int R = NB*NPIX;
  int row = blockIdx.x;            // b*N + m
  int mr  = row % NPIX;
  const float* e  = E  + (long)row * NPIX;
  const float* m1 = M1 + (long)mr  * NPIX;
  const float* m2 = M2 + (long)mr  * NPIX;
  int tid = threadIdx.x;

  float ev[9], w1[9], w2[9];
  float mx0=-3.4e38f, mx1=-3.4e38f, mx2=-3.4e38f;
  #pragma unroll
  for (int i=0;i<9;i++){
    int n = tid + i*256;
    ev[i]=e[n]; w1[i]=m1[n]; w2[i]=m2[n];
    mx0 = fmaxf(mx0, ev[i]);
    if (w1[i] > 0.f) mx1 = fmaxf(mx1, ev[i]);
    if (w2[i] > 0.f) mx2 = fmaxf(mx2, ev[i]);
  }
  mx0 = blockMax(mx0, sh);
  mx1 = blockMax(mx1, sh);
  mx2 = blockMax(mx2, sh);
  float s0=0.f, s1=0.f, s2=0.f;
  #pragma unroll
  for (int i=0;i<9;i++){
    s0 += __expf(ev[i]-mx0);
    s1 += (w1[i] > 0.f) ? __expf(ev[i]-mx1) : 0.f;
    s2 += (w2[i] > 0.f) ? __expf(ev[i]-mx2) : 0.f;
  }
  s0 = blockSum(s0, sh);
  s1 = blockSum(s1, sh);
  s2 = blockSum(s2, sh);
  if (tid == 0){
    st[row]       = mx0;  st[R   + row] = 1.f/s0;
    st[2*R + row] = mx1;  st[3*R + row] = 1.f/s1;
    st[4*R + row] = mx2;  st[5*R + row] = 1.f/s2;
  }
}

// ---------------- materialize attention matrix ----------------
__global__ __launch_bounds__(256) void attn_mat_kernel(
    const float* __restrict__ E, const float* __restrict__ mask,
    const float* __restrict__ st, float* __restrict__ A, long total4)
{
  const long NN2 = (long)NPIX*NPIX;
  long i4 = (long)blockIdx.x * 256 + threadIdx.x;
  if (i4 >= total4) return;
  long idx = i4 * 4;
  int  b   = (int)(idx / NN2);
  long rem = idx - (long)b * NN2;
  int  mr  = (int)(rem / NPIX);
  float mx   = st[b*NPIX + mr];
  float rinv = st[NB*NPIX + b*NPIX + mr];
  float4 e = *(const float4*)&E[idx];
  float4 a;
  a.x = __expf(e.x-mx)*rinv;
  a.y = __expf(e.y-mx)*rinv;
  a.z = __expf(e.z-mx)*rinv;
  a.w = __expf(e.w-mx)*rinv;
  if (mask){
    float4 mk = *(const float4*)&mask[rem];
    if (mk.x <= 0.f) a.x = 0.f;
    if (mk.y <= 0.f) a.y = 0.f;
    if (mk.z <= 0.f) a.z = 0.f;
    if (mk.w <= 0.f) a.w = 0.f;
  }
  *(float4*)&A[idx] = a;
}

// ---------------- chl softmax: attn[o,c] = softmax_c(rowmax - expand[o,c]) ----------------
__global__ __launch_bounds__(256) void chl_softmax_kernel(
    const float* __restrict__ E, float* __restrict__ A)
{
  __shared__ float sh[32];
  long row = blockIdx.x;
  const float* e = E + row * CCH;
  float* a = A + row * CCH;
  int tid = threadIdx.x;
  float v0 = e[tid], v1 = e[tid+256];
  float mn = blockMin(fminf(v0, v1), sh);   // softmax(max-e) == exp(mn-e)/sum
  float t0 = __expf(mn - v0), t1 = __expf(mn - v1);
  float s = blockSum(t0 + t1, sh);
  float rinv = 1.f/s;
  a[tid]     = t0*rinv;
  a[tid+256] = t1*rinv;
}

// ---------------- im2col: X (B,512,48,48) -> Cols (B,4608,2304), SAME pad ----------------
__global__ __launch_bounds__(256) void im2col_kernel(const float* __restrict__ X,
                                                     float* __restrict__ Cols)
{
  long idx = (long)blockIdx.x * 256 + threadIdx.x;
  const long total = (long)NB*KCONV*NPIX;
  if (idx >= total) return;
  int n = (int)(idx % NPIX);
  long t = idx / NPIX;
  int kk = (int)(t % 9);
  long t2 = t / 9;
  int ic = (int)(t2 % CCH);
  int b  = (int)(t2 / CCH);
  int y = n / HW, x = n - y*HW;
  int ky = kk / 3, kx = kk - ky*3;
  int sy = y + ky - 1, sx = x + kx - 1;
  float v = 0.f;
  if (sy >= 0 && sy < HW && sx >= 0 && sx < HW)
    v = X[((long)(b*CCH + ic))*NPIX + sy*HW + sx];
  Cols[idx] = v;
}

// ---------------- host side ----------------
template<int MODE, int EPI>
static void rungemm(const float* A, long sA, const float* B, long sB, float* C, long sC,
                    int M, int N, int K,
                    const float* p0, const float* p1,
                    const float* res, long sRes, const float* gamma)
{
  dim3 grid(N/128, (M+127)/128, NB);
  gemm2_kernel<MODE,EPI><<<grid, 256>>>(A, sA, B, sB, C, sC, M, N, K,
                                        p0, p1, res, sRes, gamma);
}

static float* sym(const void* s){
  void* p = nullptr;
  cudaGetSymbolAddress(&p, s);
  return (float*)p;
}

extern "C" void kernel_launch(void* const* d_in, const int* in_sizes, int n_in,
                              void* d_out, int out_size)
{
  const float* x       = (const float*)d_in[0];
  const float* wq      = (const float*)d_in[1];
  const float* bq      = (const float*)d_in[2];
  const float* wk      = (const float*)d_in[3];
  const float* bk      = (const float*)d_in[4];
  const float* wv0     = (const float*)d_in[5];
  const float* bv0     = (const float*)d_in[6];
  const float* conv1_w = (const float*)d_in[7];
  const float* conv1_s = (const float*)d_in[8];
  const float* conv1_b = (const float*)d_in[9];
  const float* conv2_w = (const float*)d_in[10];
  const float* conv2_s = (const float*)d_in[11];
  const float* conv2_b = (const float*)d_in[12];
  const float* gamma   = (const float*)d_in[13];
  const float* gamma1  = (const float*)d_in[14];
  const float* gamma2  = (const float*)d_in[15];
  const float* c1_qw   = (const float*)d_in[16];
  const float* c1_qs   = (const float*)d_in[17];
  const float* c1_qb   = (const float*)d_in[18];
  const float* c1_ew   = (const float*)d_in[19];
  const float* c1_eb   = (const float*)d_in[20];
  const float* c2_qw   = (const float*)d_in[21];
  const float* c2_qs   = (const float*)d_in[22];
  const float* c2_qb   = (const float*)d_in[23];
  const float* c2_ew   = (const float*)d_in[24];
  const float* c2_eb   = (const float*)d_in[25];
  const float* mask1   = (const float*)d_in[26];
  const float* mask2   = (const float*)d_in[27];

  float* q    = sym(g_q);     float* k    = sym(g_k);     float* v     = sym(g_v);
  float* E    = sym(g_E);     float* A    = sym(g_A);     float* st    = sym(g_stats);
  float* buf0 = sym(g_buf0);  float* buf1 = sym(g_buf1);  float* out1  = sym(g_out1);
  float* vchl = sym(g_vchl);  float* qc   = sym(g_qc);    float* E2    = sym(g_E2);
  float* expd = sym(g_expand);float* attnc= sym(g_attnc); float* cols  = sym(g_cols);
  float* out  = (float*)d_out;

  const long sX  = (long)CCH*NPIX;
  const long sQ  = (long)CR*NPIX;
  const long sE  = (long)NPIX*NPIX;
  const long sQC = (long)CH4*NPIX;
  const long sE2 = (long)CH4*CCH;
  const long sCC = (long)CCH*CCH;
  const long sCOL= (long)KCONV*NPIX;
  const int  R   = NB*NPIX;
  const long total4 = (long)NB*NPIX*NPIX/4;
  const int  amg = (int)((total4 + 255)/256);
  const long colTotal = (long)NB*KCONV*NPIX;
  const int  colg = (int)((colTotal + 255)/256);

  // Q, K, V (1x1 convs)
  rungemm<0,0>(wq, 0, x, sX, q, sQ, CR,  NPIX, CCH, bq,  nullptr, nullptr, 0, nullptr);
  rungemm<0,0>(wk, 0, x, sX, k, sQ, CR,  NPIX, CCH, bk,  nullptr, nullptr, 0, nullptr);
  rungemm<0,0>(wv0,0, x, sX, v, sX, CCH, NPIX, CCH, bv0, nullptr, nullptr, 0, nullptr);

  // energy = Q^T K
  rungemm<1,0>(q, sQ, k, sQ, E, sE, NPIX, NPIX, CR, nullptr, nullptr, nullptr, 0, nullptr);

  // softmax stats for all 3 variants
  softmax_stats_kernel<<<R, 256>>>(E, mask1, mask2, st);

  // ---- pass 0 (unmasked) ----
  attn_mat_kernel<<<amg, 256>>>(E, nullptr, st, A, total4);
  rungemm<2,2>(v, sX, A, sE, buf1, sX, CCH, NPIX, NPIX, nullptr, nullptr, x, sX, gamma);
  im2col_kernel<<<colg, 256>>>(buf1, cols);
  rungemm<0,1>(conv1_w, 0, cols, sCOL, buf0, sX, CCH, NPIX, KCONV, conv1_s, conv1_b, nullptr, 0, nullptr);

  // chl #1 on out0
  rungemm<0,1>(c1_qw, 0, buf0, sX, qc, sQC, CH4, NPIX, CCH, c1_qs, c1_qb, nullptr, 0, nullptr);
  rungemm<2,0>(qc, sQC, buf0, sX, E2, sE2, CH4, CCH, NPIX, nullptr, nullptr, nullptr, 0, nullptr);
  rungemm<0,0>(c1_ew, 0, E2, sE2, expd, sCC, CCH, CCH, CH4, c1_eb, nullptr, nullptr, 0, nullptr);
  chl_softmax_kernel<<<NB*CCH, 256>>>(expd, attnc);
  rungemm<0,0>(attnc, sCC, buf0, sX, vchl, sX, CCH, NPIX, CCH, nullptr, nullptr, nullptr, 0, nullptr);

  // ---- pass 1 (mask1) ----
  attn_mat_kernel<<<amg, 256>>>(E, mask1, st + 2*R, A, total4);
  rungemm<2,2>(vchl, sX, A, sE, buf1, sX, CCH, NPIX, NPIX, nullptr, nullptr, buf0, sX, gamma1);
  im2col_kernel<<<colg, 256>>>(buf1, cols);
  rungemm<0,1>(conv2_w, 0, cols, sCOL, out1, sX, CCH, NPIX, KCONV, conv2_s, conv2_b, nullptr, 0, nullptr);

  // chl #2 on out1
  rungemm<0,1>(c2_qw, 0, out1, sX, qc, sQC, CH4, NPIX, CCH, c2_qs, c2_qb, nullptr, 0, nullptr);
  rungemm<2,0>(qc, sQC, out1, sX, E2, sE2, CH4, CCH, NPIX, nullptr, nullptr, nullptr, 0, nullptr);
  rungemm<0,0>(c2_ew, 0, E2, sE2, expd, sCC, CCH, CCH, CH4, c2_eb, nullptr, nullptr, 0, nullptr);
  chl_softmax_kernel<<<NB*CCH, 256>>>(expd, attnc);
  rungemm<0,0>(attnc, sCC, out1, sX, vchl, sX, CCH, NPIX, CCH, nullptr, nullptr, nullptr, 0, nullptr);

  // ---- pass 2 (mask2) -> final output ----
  attn_mat_kernel<<<amg, 256>>>(E, mask2, st + 4*R, A, total4);
  rungemm<2,2>(vchl, sX, A, sE, out, sX, CCH, NPIX, NPIX, nullptr, nullptr, out1, sX, gamma2);

  (void)in_sizes; (void)n_in; (void)out_size;
}